// round 7
// baseline (speedup 1.0000x reference)
#include <cuda_runtime.h>

// LogicConv3d: B=16, C=3, H=W=32, K=64, P=784, S=64, 7-level soft logic tree.
// d_in: [0]=x f32[16,3,32,32], [1..7]=w0..w6 f32[2^(6-l),64,16],
//       [8]=left_idx i32[64,784,64,3], [9]=right_idx i32[64,784,64,3]
// d_out: f32[16,64,784,1]

#define B_ 16
#define C_ 3
#define HW_ 1024
#define CHW_ 3072
#define K_ 64
#define P_ 784
#define KP_ (K_ * P_)     // 50176
#define NROWS 127
#define TP 16             // patches per block (784 = 49*16)

// scratch
__device__ float g_coef[K_ * NROWS * 8];  // per-(k,node) SPLATTED coeffs:
                                          // {c0,c0,c1,c1,c2,c2,c3,c3}
__device__ float g_xt[CHW_ * B_];         // x transposed: [offset][batch] (192KB)

__constant__ float G4[16][4] = {
    {0,0,0,0},{0,0,0,1},{0,1,0,-1},{0,1,0,0},
    {0,0,1,-1},{0,0,1,0},{0,1,1,-2},{0,1,1,-1},
    {1,-1,-1,1},{1,-1,-1,2},{1,0,-1,0},{1,0,-1,1},
    {1,-1,0,0},{1,-1,0,1},{1,0,0,-1},{1,0,0,0}};

// ---------------------------------------------------------------------------
// Prep (tiny): softmax coeffs (splatted for f32x2) + x transpose.
// ---------------------------------------------------------------------------
__global__ void prep_kernel(const float* __restrict__ x,
                            const float* __restrict__ w0, const float* __restrict__ w1,
                            const float* __restrict__ w2, const float* __restrict__ w3,
                            const float* __restrict__ w4, const float* __restrict__ w5,
                            const float* __restrict__ w6) {
    int r = blockIdx.x * 256 + threadIdx.x;
    if (r < NROWS * K_) {
        int row = r >> 6;
        int k   = r & 63;
        int bse = 0, n = 64, l = 0;
        while (row >= bse + n) { bse += n; n >>= 1; ++l; }
        int s = row - bse;
        const float* ws[7] = {w0, w1, w2, w3, w4, w5, w6};
        const float* p = ws[l] + (s * K_ + k) * 16;
        float v[16], m = -1e30f;
#pragma unroll
        for (int i = 0; i < 16; ++i) { v[i] = p[i]; m = fmaxf(m, v[i]); }
        float sum = 0.f, c0 = 0.f, c1 = 0.f, c2 = 0.f, c3 = 0.f;
#pragma unroll
        for (int i = 0; i < 16; ++i) {
            float e = expf(v[i] - m);
            sum += e;
            c0 += e * G4[i][0]; c1 += e * G4[i][1];
            c2 += e * G4[i][2]; c3 += e * G4[i][3];
        }
        float inv = 1.f / sum;
        c0 *= inv; c1 *= inv; c2 *= inv; c3 *= inv;
        float4* dst = (float4*)(g_coef + (k * NROWS + row) * 8);
        dst[0] = make_float4(c0, c0, c1, c1);
        dst[1] = make_float4(c2, c2, c3, c3);
        return;
    }
    r -= NROWS * K_;
    if (r < CHW_ * B_) {
        int b = r & 15, off = r >> 4;
        g_xt[r] = x[b * CHW_ + off];
    }
}

// ---------------------------------------------------------------------------
// Main kernel: 128 threads = 8 batch-pairs (packed f32x2) x 16 patches, one k.
// Offsets pre-scaled to BYTE offsets (int2, LDS.64, conflict-free).
// Gates use fma.rn.f32x2 (3 packed FMAs per gate) with pre-splatted coeffs
// kept in SMEM -> ~30% fewer issue slots per node than R5.
// ---------------------------------------------------------------------------
typedef unsigned long long u64;

__device__ __forceinline__ u64 gate2p(u64 a, u64 b, const ulonglong2* cp) {
    ulonglong2 c01 = cp[0];   // .x=(c0,c0) .y=(c1,c1)
    ulonglong2 c23 = cp[1];   // .x=(c2,c2) .y=(c3,c3)
    u64 t1, t2, v;
    asm("fma.rn.f32x2 %0, %1, %2, %3;" : "=l"(t1) : "l"(c01.y), "l"(a), "l"(c01.x));
    asm("fma.rn.f32x2 %0, %1, %2, %3;" : "=l"(t2) : "l"(c23.y), "l"(a), "l"(c23.x));
    asm("fma.rn.f32x2 %0, %1, %2, %3;" : "=l"(v)  : "l"(b),     "l"(t2), "l"(t1));
    return v;
}

__global__ __launch_bounds__(128, 10)
void logic_kernel(const int* __restrict__ lidx,
                  const int* __restrict__ ridx,
                  float* __restrict__ out) {
    __shared__ int2       soff[TP][65];      // [patch][s] = (left,right) BYTE offsets
    __shared__ ulonglong2 scoef[NROWS * 2];  // splatted coeffs, 32B/node

    const int k   = blockIdx.y;
    const int p0  = blockIdx.x * TP;
    const int tid = threadIdx.x;

    // coefficients for this k (4KB contiguous)
    {
        const float4* gc = (const float4*)g_coef + (long)k * NROWS * 2;
        float4* sc = (float4*)scoef;
#pragma unroll
        for (int i = tid; i < NROWS * 2; i += 128) sc[i] = gc[i];
    }

    // decode idx triples -> byte offsets (coalesced, shared across all b)
    {
        const int* lb = lidx + (k * P_ + p0) * (64 * 3);
        const int* rb = ridx + (k * P_ + p0) * (64 * 3);
#pragma unroll
        for (int e = tid; e < TP * 64; e += 128) {
            int pl = e >> 6, s = e & 63;
            int h = lb[3 * e], w = lb[3 * e + 1], c = lb[3 * e + 2];
            int lo = (c * HW_ + h * 32 + w) << 6;
            h = rb[3 * e]; w = rb[3 * e + 1]; c = rb[3 * e + 2];
            int ro = (c * HW_ + h * 32 + w) << 6;
            soff[pl][s] = make_int2(lo, ro);
        }
    }
    __syncthreads();

    const int bg2 = tid & 7;           // batch pair (2 floats, packed)
    const int pl  = tid >> 3;          // patch lane 0..15
    const char* xtb = (const char*)g_xt + bg2 * 8;

    u64 st[7];
    int sp = 0;
#pragma unroll
    for (int s = 0; s < 64; ++s) {
        int2 o = soff[pl][s];
        u64 A  = *(const u64*)(xtb + o.x);
        u64 Bv = *(const u64*)(xtb + o.y);
        u64 v = gate2p(A, Bv, &scoef[2 * s]);
#pragma unroll
        for (int l = 1; l <= 6; ++l) {
            if (((s + 1) & ((1 << l) - 1)) == 0) {
                int node = (128 - (128 >> l)) + (s >> l);
                v = gate2p(st[--sp], v, &scoef[2 * node]);
            }
        }
        st[sp++] = v;
    }

    float2 r = *(float2*)&st[0];
    long ob0 = (long)(bg2 * 2) * KP_ + k * P_ + p0 + pl;
    out[ob0]       = r.x;
    out[ob0 + KP_] = r.y;
}

// ---------------------------------------------------------------------------
extern "C" void kernel_launch(void* const* d_in, const int* in_sizes, int n_in,
                              void* d_out, int out_size) {
    const float* x  = (const float*)d_in[0];
    const float* w0 = (const float*)d_in[1];
    const float* w1 = (const float*)d_in[2];
    const float* w2 = (const float*)d_in[3];
    const float* w3 = (const float*)d_in[4];
    const float* w4 = (const float*)d_in[5];
    const float* w5 = (const float*)d_in[6];
    const float* w6 = (const float*)d_in[7];
    const int* lidx = (const int*)d_in[8];
    const int* ridx = (const int*)d_in[9];
    float* out = (float*)d_out;

    int prep_work = NROWS * K_ + CHW_ * B_;           // 57280
    prep_kernel<<<(prep_work + 255) / 256, 256>>>(x, w0, w1, w2, w3, w4, w5, w6);
    logic_kernel<<<dim3(P_ / TP, K_), 128>>>(lidx, ridx, out);
}

// round 8
// speedup vs baseline: 1.3775x; 1.3775x over previous
#include <cuda_runtime.h>
#include <cuda_fp16.h>

// LogicConv3d: B=16, C=3, H=W=32, K=64, P=784, S=64, 7-level soft logic tree.
// d_in: [0]=x f32[16,3,32,32], [1..7]=w0..w6 f32[2^(6-l),64,16],
//       [8]=left_idx i32[64,784,64,3], [9]=right_idx i32[64,784,64,3]
// d_out: f32[16,64,784,1]

#define B_ 16
#define C_ 3
#define HW_ 1024
#define CHW_ 3072
#define K_ 64
#define P_ 784
#define KP_ (K_ * P_)     // 50176
#define NROWS 127
#define TP 16             // patches per block (784 = 49*16)

// scratch
__device__ float4 g_coef[K_ * NROWS];     // per-(k,node) gate coeffs (fp32)
__device__ __half g_xth[CHW_ * B_];       // x transposed fp16: [offset][batch] (96KB)

__constant__ float G4[16][4] = {
    {0,0,0,0},{0,0,0,1},{0,1,0,-1},{0,1,0,0},
    {0,0,1,-1},{0,0,1,0},{0,1,1,-2},{0,1,1,-1},
    {1,-1,-1,1},{1,-1,-1,2},{1,0,-1,0},{1,0,-1,1},
    {1,-1,0,0},{1,-1,0,1},{1,0,0,-1},{1,0,0,0}};

// ---------------------------------------------------------------------------
// Prep (tiny): softmax coeffs + fp16 x transpose.
// ---------------------------------------------------------------------------
__global__ void prep_kernel(const float* __restrict__ x,
                            const float* __restrict__ w0, const float* __restrict__ w1,
                            const float* __restrict__ w2, const float* __restrict__ w3,
                            const float* __restrict__ w4, const float* __restrict__ w5,
                            const float* __restrict__ w6) {
    int r = blockIdx.x * 256 + threadIdx.x;
    if (r < NROWS * K_) {
        int row = r >> 6;
        int k   = r & 63;
        int bse = 0, n = 64, l = 0;
        while (row >= bse + n) { bse += n; n >>= 1; ++l; }
        int s = row - bse;
        const float* ws[7] = {w0, w1, w2, w3, w4, w5, w6};
        const float* p = ws[l] + (s * K_ + k) * 16;
        float v[16], m = -1e30f;
#pragma unroll
        for (int i = 0; i < 16; ++i) { v[i] = p[i]; m = fmaxf(m, v[i]); }
        float sum = 0.f, c0 = 0.f, c1 = 0.f, c2 = 0.f, c3 = 0.f;
#pragma unroll
        for (int i = 0; i < 16; ++i) {
            float e = expf(v[i] - m);
            sum += e;
            c0 += e * G4[i][0]; c1 += e * G4[i][1];
            c2 += e * G4[i][2]; c3 += e * G4[i][3];
        }
        float inv = 1.f / sum;
        g_coef[k * NROWS + row] = make_float4(c0 * inv, c1 * inv, c2 * inv, c3 * inv);
        return;
    }
    r -= NROWS * K_;
    if (r < CHW_ * B_) {
        int b = r & 15, off = r >> 4;
        g_xth[r] = __float2half(x[b * CHW_ + off]);
    }
}

// ---------------------------------------------------------------------------
// Main kernel: 128 threads = 8 batch-pairs x 16 patches, one k.
// xt is fp16 -> each row is 32B, so a warp's 4 consecutive patches span
// 128B = 1-2 cache lines per gather side (half the wavefronts of fp32 xt).
// Values are loaded as half2, converted once, and the whole tree runs fp32.
// ---------------------------------------------------------------------------
__device__ __forceinline__ float2 gate2(float2 a, float2 b, float4 c) {
    float2 r;
    r.x = fmaf(b.x, fmaf(c.w, a.x, c.z), fmaf(c.y, a.x, c.x));
    r.y = fmaf(b.y, fmaf(c.w, a.y, c.z), fmaf(c.y, a.y, c.x));
    return r;
}

__global__ __launch_bounds__(128, 12)
void logic_kernel(const int* __restrict__ lidx,
                  const int* __restrict__ ridx,
                  float* __restrict__ out) {
    __shared__ int2   soff[TP][65];    // [patch][s] = (left,right) BYTE offsets into fp16 xt
    __shared__ float4 scoef[NROWS];

    const int k   = blockIdx.y;
    const int p0  = blockIdx.x * TP;
    const int tid = threadIdx.x;

    if (tid < NROWS) scoef[tid] = g_coef[k * NROWS + tid];

    // decode idx triples -> byte offsets (row*32), coalesced, shared across b
    {
        const int* lb = lidx + (k * P_ + p0) * (64 * 3);
        const int* rb = ridx + (k * P_ + p0) * (64 * 3);
#pragma unroll
        for (int e = tid; e < TP * 64; e += 128) {
            int pl = e >> 6, s = e & 63;
            int h = lb[3 * e], w = lb[3 * e + 1], c = lb[3 * e + 2];
            int lo = (c * HW_ + h * 32 + w) << 5;
            h = rb[3 * e]; w = rb[3 * e + 1]; c = rb[3 * e + 2];
            int ro = (c * HW_ + h * 32 + w) << 5;
            soff[pl][s] = make_int2(lo, ro);
        }
    }
    __syncthreads();

    const int bg2 = tid & 7;           // batch pair (2 batches, half2)
    const int pl  = tid >> 3;          // patch lane 0..15 (consecutive in warp)
    const char* xtb = (const char*)g_xth + bg2 * 4;

    float2 st[7];
    int sp = 0;
#pragma unroll
    for (int s = 0; s < 64; ++s) {
        int2 o = soff[pl][s];
        half2 a2 = *(const half2*)(xtb + o.x);
        half2 b2 = *(const half2*)(xtb + o.y);
        float2 A  = __half22float2(a2);
        float2 Bv = __half22float2(b2);
        float2 v = gate2(A, Bv, scoef[s]);
#pragma unroll
        for (int l = 1; l <= 6; ++l) {
            if (((s + 1) & ((1 << l) - 1)) == 0) {
                v = gate2(st[--sp], v, scoef[(128 - (128 >> l)) + (s >> l)]);
            }
        }
        st[sp++] = v;
    }

    float2 r = st[0];
    long ob0 = (long)(bg2 * 2) * KP_ + k * P_ + p0 + pl;
    out[ob0]       = r.x;
    out[ob0 + KP_] = r.y;
}

// ---------------------------------------------------------------------------
extern "C" void kernel_launch(void* const* d_in, const int* in_sizes, int n_in,
                              void* d_out, int out_size) {
    const float* x  = (const float*)d_in[0];
    const float* w0 = (const float*)d_in[1];
    const float* w1 = (const float*)d_in[2];
    const float* w2 = (const float*)d_in[3];
    const float* w3 = (const float*)d_in[4];
    const float* w4 = (const float*)d_in[5];
    const float* w5 = (const float*)d_in[6];
    const float* w6 = (const float*)d_in[7];
    const int* lidx = (const int*)d_in[8];
    const int* ridx = (const int*)d_in[9];
    float* out = (float*)d_out;

    int prep_work = NROWS * K_ + CHW_ * B_;           // 57280
    prep_kernel<<<(prep_work + 255) / 256, 256>>>(x, w0, w1, w2, w3, w4, w5, w6);
    logic_kernel<<<dim3(P_ / TP, K_), 128>>>(lidx, ridx, out);
}